// round 2
// baseline (speedup 1.0000x reference)
#include <cuda_runtime.h>
#include <cuda_bf16.h>
#include <math.h>

// Problem constants
#define Bm 256      // batch
#define Tt 128      // timesteps
#define Ff 1280     // features
#define Hh 256      // hidden
#define G4 1024     // 4*H

// ---------------------------------------------------------------------------
// Scratch (allocation-free: __device__ globals)
// ---------------------------------------------------------------------------
__device__ float g_xz[(size_t)Bm * Tt * G4];   // precomputed x@W + bias, [B*T, 4H]
__device__ float g_h[2][Bm * Hh];              // ping-pong hidden state
__device__ float g_c[Bm * Hh];                 // cell state (in-place)

// ---------------------------------------------------------------------------
// Init: zero h0, c0
// ---------------------------------------------------------------------------
__global__ void init_state_kernel() {
    int idx = blockIdx.x * blockDim.x + threadIdx.x;
    if (idx < Bm * Hh) {
        g_h[0][idx] = 0.0f;
        g_c[idx]    = 0.0f;
    }
}

// ---------------------------------------------------------------------------
// Phase 1: xz = x @ W + bias   (M=32768, K=1280, N=1024)
// 128x128 tile, BK=16, 256 threads, 8x8 micro-tile.
// Register-staged double buffering: prefetch tile k+1 into registers while
// computing tile k from smem, hiding global-load latency.
// ---------------------------------------------------------------------------
#define BM 128
#define BN 128
#define BK 16

__global__ __launch_bounds__(256) void gemm_xz_kernel(
    const float* __restrict__ x,      // [32768, 1280]
    const float* __restrict__ W,      // [1280, 1024]
    const float* __restrict__ bias)   // [1024]
{
    __shared__ float As[BK][BM + 4];  // transposed A tile, padded
    __shared__ float Bs[BK][BN];

    const int tid = threadIdx.x;
    const int m0  = blockIdx.y * BM;
    const int n0  = blockIdx.x * BN;
    const int r0  = (tid >> 4) * 8;   // row offset in tile (0..120)
    const int c0  = (tid & 15) * 8;   // col offset in tile (0..120)

    // Per-thread load coordinates (2 float4 for A, 2 float4 for B)
    const int a_row0 = tid >> 2;               // 0..63
    const int a_q0   = tid & 3;
    const int a_row1 = (tid + 256) >> 2;       // 64..127
    const int a_q1   = tid & 3;
    const int b_kr0  = tid >> 5;               // 0..7
    const int b_q0   = tid & 31;
    const int b_kr1  = (tid + 256) >> 5;       // 8..15
    const int b_q1   = tid & 31;

    float acc[8][8];
#pragma unroll
    for (int i = 0; i < 8; i++)
#pragma unroll
        for (int j = 0; j < 8; j++) acc[i][j] = 0.0f;

    // --- Prologue: load tile 0 into registers ---
    float4 pa0 = *(const float4*)(x + (size_t)(m0 + a_row0) * Ff + 0 + a_q0 * 4);
    float4 pa1 = *(const float4*)(x + (size_t)(m0 + a_row1) * Ff + 0 + a_q1 * 4);
    float4 pb0 = *(const float4*)(W + (size_t)(0 + b_kr0) * G4 + n0 + b_q0 * 4);
    float4 pb1 = *(const float4*)(W + (size_t)(0 + b_kr1) * G4 + n0 + b_q1 * 4);

    const int NK = Ff / BK;   // 80
    for (int kt = 0; kt < NK; kt++) {
        // Commit prefetched registers to smem
        As[a_q0 * 4 + 0][a_row0] = pa0.x;
        As[a_q0 * 4 + 1][a_row0] = pa0.y;
        As[a_q0 * 4 + 2][a_row0] = pa0.z;
        As[a_q0 * 4 + 3][a_row0] = pa0.w;
        As[a_q1 * 4 + 0][a_row1] = pa1.x;
        As[a_q1 * 4 + 1][a_row1] = pa1.y;
        As[a_q1 * 4 + 2][a_row1] = pa1.z;
        As[a_q1 * 4 + 3][a_row1] = pa1.w;
        *(float4*)&Bs[b_kr0][b_q0 * 4] = pb0;
        *(float4*)&Bs[b_kr1][b_q1 * 4] = pb1;
        __syncthreads();

        // Prefetch next tile into registers (overlaps with FMA block below)
        if (kt + 1 < NK) {
            int k0n = (kt + 1) * BK;
            pa0 = *(const float4*)(x + (size_t)(m0 + a_row0) * Ff + k0n + a_q0 * 4);
            pa1 = *(const float4*)(x + (size_t)(m0 + a_row1) * Ff + k0n + a_q1 * 4);
            pb0 = *(const float4*)(W + (size_t)(k0n + b_kr0) * G4 + n0 + b_q0 * 4);
            pb1 = *(const float4*)(W + (size_t)(k0n + b_kr1) * G4 + n0 + b_q1 * 4);
        }

#pragma unroll
        for (int kk = 0; kk < BK; kk++) {
            float4 a0 = *(const float4*)&As[kk][r0];
            float4 a1 = *(const float4*)&As[kk][r0 + 4];
            float4 b0 = *(const float4*)&Bs[kk][c0];
            float4 b1 = *(const float4*)&Bs[kk][c0 + 4];
            float ar[8] = {a0.x, a0.y, a0.z, a0.w, a1.x, a1.y, a1.z, a1.w};
            float br[8] = {b0.x, b0.y, b0.z, b0.w, b1.x, b1.y, b1.z, b1.w};
#pragma unroll
            for (int i = 0; i < 8; i++)
#pragma unroll
                for (int j = 0; j < 8; j++) acc[i][j] = fmaf(ar[i], br[j], acc[i][j]);
        }
        __syncthreads();
    }

    // Epilogue: add bias, store
    float bv[8];
#pragma unroll
    for (int j = 0; j < 8; j++) bv[j] = bias[n0 + c0 + j];

#pragma unroll
    for (int i = 0; i < 8; i++) {
        size_t rowoff = (size_t)(m0 + r0 + i) * G4 + n0 + c0;
        float4 v0, v1;
        v0.x = acc[i][0] + bv[0]; v0.y = acc[i][1] + bv[1];
        v0.z = acc[i][2] + bv[2]; v0.w = acc[i][3] + bv[3];
        v1.x = acc[i][4] + bv[4]; v1.y = acc[i][5] + bv[5];
        v1.z = acc[i][6] + bv[6]; v1.w = acc[i][7] + bv[7];
        *(float4*)(g_xz + rowoff)     = v0;
        *(float4*)(g_xz + rowoff + 4) = v1;
    }
}

// ---------------------------------------------------------------------------
// Phase 2: one timestep.
//   z = xz[:, t, :] + h_prev @ R;  gates; c, h update.
// Grid: (8 h-col tiles of 32) x (16 batch tiles of 16) = 128 CTAs, 256 threads.
// z-tile = 16 rows x 128 cols where col c -> global gate col ((c>>5)*256 + hc0 + (c&31)),
// so each CTA holds all 4 gates for its (row, h-col) patch -> fully fused update.
// ---------------------------------------------------------------------------
__device__ __forceinline__ float sigf(float v) {
    return 1.0f / (1.0f + expf(-v));
}

__global__ __launch_bounds__(256) void lstm_step_kernel(
    const float* __restrict__ R,    // [256, 1024]
    float* __restrict__ out,        // [256, 256] final output (written at t==127)
    int t)
{
    __shared__ float As[16][16];     // h_prev chunk, transposed: As[k][m]
    __shared__ float Bs[16][128];    // R chunk, gathered gate columns
    __shared__ float Zs[16][128];    // z tile for gate fusion

    const float* __restrict__ hprev = g_h[t & 1];
    float*       __restrict__ hnext = g_h[(t + 1) & 1];

    const int tid = threadIdx.x;
    const int hc0 = blockIdx.x * 32;   // h-column tile base
    const int b0  = blockIdx.y * 16;   // batch tile base
    const int tx  = tid & 31;          // col group: cols tx*4 .. tx*4+3
    const int ty  = tid >> 5;          // row group: rows ty*2, ty*2+1

    float acc[2][4];
#pragma unroll
    for (int i = 0; i < 2; i++)
#pragma unroll
        for (int j = 0; j < 4; j++) acc[i][j] = 0.0f;

    for (int k0 = 0; k0 < Hh; k0 += 16) {
        // Load h chunk: 16 rows x 16 k, transposed
        {
            int m = tid >> 4;   // 0..15
            int k = tid & 15;   // 0..15
            As[k][m] = hprev[(b0 + m) * Hh + k0 + k];
        }
        // Load R chunk: 16 k-rows x 128 gathered cols
#pragma unroll
        for (int i = 0; i < 8; i++) {
            int e  = tid + i * 256;        // 0..2047
            int kr = e >> 7;               // 0..15
            int cc = e & 127;              // 0..127
            int gcol = ((cc >> 5) << 8) + hc0 + (cc & 31);
            Bs[kr][cc] = R[(k0 + kr) * G4 + gcol];
        }
        __syncthreads();

#pragma unroll
        for (int kk = 0; kk < 16; kk++) {
            float a0 = As[kk][ty * 2];
            float a1 = As[kk][ty * 2 + 1];
            float4 b4 = *(const float4*)&Bs[kk][tx * 4];
            float br[4] = {b4.x, b4.y, b4.z, b4.w};
#pragma unroll
            for (int j = 0; j < 4; j++) {
                acc[0][j] = fmaf(a0, br[j], acc[0][j]);
                acc[1][j] = fmaf(a1, br[j], acc[1][j]);
            }
        }
        __syncthreads();
    }

    // Add xz and stage z tile into smem
#pragma unroll
    for (int rr = 0; rr < 2; rr++) {
        int r = ty * 2 + rr;
#pragma unroll
        for (int j = 0; j < 4; j++) {
            int cz   = tx * 4 + j;
            int gcol = ((cz >> 5) << 8) + hc0 + (cz & 31);
            size_t xzoff = ((size_t)(b0 + r) * Tt + t) * G4 + gcol;
            Zs[r][cz] = acc[rr][j] + g_xz[xzoff];
        }
    }
    __syncthreads();

    // Fused cell update: 16 rows x 32 h-cols = 512 elems, 2 per thread
#pragma unroll
    for (int i = 0; i < 2; i++) {
        int e  = tid + i * 256;     // 0..511
        int r  = e >> 5;            // 0..15
        int hh = e & 31;            // 0..31
        float zi = Zs[r][hh];
        float zf = Zs[r][32 + hh];
        float zg = Zs[r][64 + hh];
        float zo = Zs[r][96 + hh];

        int idx = (b0 + r) * Hh + hc0 + hh;
        float cn = sigf(zf) * g_c[idx] + sigf(zi) * tanhf(zg);
        g_c[idx] = cn;
        float hn = sigf(zo) * tanhf(cn);
        hnext[idx] = hn;
        if (t == Tt - 1) out[idx] = hn;
    }
}

// ---------------------------------------------------------------------------
// Launch
// ---------------------------------------------------------------------------
extern "C" void kernel_launch(void* const* d_in, const int* in_sizes, int n_in,
                              void* d_out, int out_size)
{
    const float* x    = (const float*)d_in[0];   // [256, 128, 1280]
    const float* W    = (const float*)d_in[1];   // [1280, 1024]
    const float* R    = (const float*)d_in[2];   // [256, 1024]
    const float* bias = (const float*)d_in[3];   // [1024]
    float* out = (float*)d_out;                  // [256, 256]

    (void)in_sizes; (void)n_in; (void)out_size;

    // Zero h0 / c0
    init_state_kernel<<<(Bm * Hh + 511) / 512, 512>>>();

    // Phase 1: xz = x @ W + bias
    gemm_xz_kernel<<<dim3(G4 / BN, (Bm * Tt) / BM), 256>>>(x, W, bias);

    // Phase 2: 128 sequential timesteps (kernel boundary = grid-wide sync)
    for (int t = 0; t < Tt; t++) {
        lstm_step_kernel<<<dim3(Hh / 32, Bm / 16), 256>>>(R, out, t);
    }
}

// round 3
// speedup vs baseline: 1.2693x; 1.2693x over previous
#include <cuda_runtime.h>
#include <cuda_bf16.h>
#include <math.h>
#include <stdint.h>

// Problem constants
#define Bm 256      // batch
#define Tt 128      // timesteps
#define Ff 1280     // features
#define Hh 256      // hidden
#define G4 1024     // 4*H

// ---------------------------------------------------------------------------
// Scratch (allocation-free: __device__ globals)
// ---------------------------------------------------------------------------
__device__ float g_xz[(size_t)Bm * Tt * G4];          // x@W + bias, [B*T, 4H]
__device__ float g_h[2][Bm * Hh];                      // ping-pong hidden state
__device__ float g_c[Bm * Hh];                         // cell state
__device__ __nv_bfloat16 g_Wt_hi[(size_t)G4 * Ff];     // W^T hi split, [1024][1280]
__device__ __nv_bfloat16 g_Wt_lo[(size_t)G4 * Ff];     // W^T lo split

// ---------------------------------------------------------------------------
// Init: zero h0, c0
// ---------------------------------------------------------------------------
__global__ void init_state_kernel() {
    int idx = blockIdx.x * blockDim.x + threadIdx.x;
    if (idx < Bm * Hh) {
        g_h[0][idx] = 0.0f;
        g_c[idx]    = 0.0f;
    }
}

// ---------------------------------------------------------------------------
// W transpose + bf16 hi/lo split: Wt[n][k] = split(W[k][n])
// ---------------------------------------------------------------------------
__global__ __launch_bounds__(256) void convert_w_kernel(const float* __restrict__ W) {
    __shared__ float tile[32][33];
    const int nb = blockIdx.x * 32;   // n tile base (0..1023)
    const int kb = blockIdx.y * 32;   // k tile base (0..1279)
    const int tx = threadIdx.x;       // 0..31
    const int ty = threadIdx.y;       // 0..7

#pragma unroll
    for (int j = 0; j < 32; j += 8)
        tile[ty + j][tx] = W[(size_t)(kb + ty + j) * G4 + nb + tx];
    __syncthreads();

#pragma unroll
    for (int j = 0; j < 32; j += 8) {
        float v = tile[tx][ty + j];
        __nv_bfloat16 hi = __float2bfloat16_rn(v);
        __nv_bfloat16 lo = __float2bfloat16_rn(v - __bfloat162float(hi));
        size_t off = (size_t)(nb + ty + j) * Ff + kb + tx;
        g_Wt_hi[off] = hi;
        g_Wt_lo[off] = lo;
    }
}

// ---------------------------------------------------------------------------
// Phase 1: xz = x @ W + bias via split-bf16 mma.sync (3 products)
// Block tile 128x128, BK=32, 256 threads = 8 warps as 2(m) x 4(n),
// warp tile 64x32 = 4x4 m16n8 tiles. Smem row stride 40 halves (20 u32):
// conflict-free fragment LDS.
// ---------------------------------------------------------------------------
#define SROW 20   // smem row stride in uint32 (40 bf16 halves)

__device__ __forceinline__ uint32_t pack_bf16(__nv_bfloat16 a, __nv_bfloat16 b) {
    uint32_t lo16 = (uint32_t)__bfloat16_as_ushort(a);
    uint32_t hi16 = (uint32_t)__bfloat16_as_ushort(b);
    return lo16 | (hi16 << 16);
}

__device__ __forceinline__ void mma16816(
    float& d0, float& d1, float& d2, float& d3,
    uint32_t a0, uint32_t a1, uint32_t a2, uint32_t a3,
    uint32_t b0, uint32_t b1)
{
    asm volatile(
        "mma.sync.aligned.m16n8k16.row.col.f32.bf16.bf16.f32 "
        "{%0,%1,%2,%3}, {%4,%5,%6,%7}, {%8,%9}, {%0,%1,%2,%3};\n"
        : "+f"(d0), "+f"(d1), "+f"(d2), "+f"(d3)
        : "r"(a0), "r"(a1), "r"(a2), "r"(a3), "r"(b0), "r"(b1));
}

__global__ __launch_bounds__(256) void gemm_xz_kernel(
    const float* __restrict__ x,      // [32768, 1280]
    const float* __restrict__ bias)   // [1024]
{
    __shared__ uint32_t As_hi[128 * SROW];
    __shared__ uint32_t As_lo[128 * SROW];
    __shared__ uint32_t Bs_hi[128 * SROW];
    __shared__ uint32_t Bs_lo[128 * SROW];

    const int tid  = threadIdx.x;
    const int lane = tid & 31;
    const int wid  = tid >> 5;
    const int wm   = wid >> 2;        // 0..1 -> m offset wm*64
    const int wn   = wid & 3;         // 0..3 -> n offset wn*32
    const int m0   = blockIdx.y * 128;
    const int n0   = blockIdx.x * 128;
    const int g    = lane >> 2;       // 0..7 (fragment group/row)
    const int kq   = lane & 3;        // 0..3 (fragment k pair)

    float acc[4][4][4];
#pragma unroll
    for (int i = 0; i < 4; i++)
#pragma unroll
        for (int j = 0; j < 4; j++)
#pragma unroll
            for (int r = 0; r < 4; r++) acc[i][j][r] = 0.0f;

    for (int k0 = 0; k0 < Ff; k0 += 32) {
        // --- Load A tile 128x32 fp32, convert to hi/lo bf16 in smem ---
#pragma unroll
        for (int i = 0; i < 4; i++) {
            int e   = tid + i * 256;      // 0..1023
            int row = e >> 3;             // 0..127
            int q   = e & 7;              // float4 slot (4 k each)
            float4 v = *(const float4*)(x + (size_t)(m0 + row) * Ff + k0 + q * 4);
            __nv_bfloat16 hx = __float2bfloat16_rn(v.x);
            __nv_bfloat16 hy = __float2bfloat16_rn(v.y);
            __nv_bfloat16 hz = __float2bfloat16_rn(v.z);
            __nv_bfloat16 hw = __float2bfloat16_rn(v.w);
            __nv_bfloat16 lx = __float2bfloat16_rn(v.x - __bfloat162float(hx));
            __nv_bfloat16 ly = __float2bfloat16_rn(v.y - __bfloat162float(hy));
            __nv_bfloat16 lz = __float2bfloat16_rn(v.z - __bfloat162float(hz));
            __nv_bfloat16 lw = __float2bfloat16_rn(v.w - __bfloat162float(hw));
            int si = row * SROW + q * 2;
            As_hi[si]     = pack_bf16(hx, hy);
            As_hi[si + 1] = pack_bf16(hz, hw);
            As_lo[si]     = pack_bf16(lx, ly);
            As_lo[si + 1] = pack_bf16(lz, lw);
        }
        // --- Load B tiles 128(n) x 32(k) bf16 from pre-split Wt ---
#pragma unroll
        for (int i = 0; i < 2; i++) {
            int e = tid + i * 256;        // 0..511
            int n = e >> 2;               // 0..127
            int q = e & 3;                // 16B slot (8 halves)
            size_t goff = (size_t)(n0 + n) * Ff + k0 + q * 8;
            *(uint4*)&Bs_hi[n * SROW + q * 4] = *(const uint4*)(g_Wt_hi + goff);
            *(uint4*)&Bs_lo[n * SROW + q * 4] = *(const uint4*)(g_Wt_lo + goff);
        }
        __syncthreads();

        // --- Two k16 steps ---
#pragma unroll
        for (int ks = 0; ks < 2; ks++) {
            uint32_t ahi[4][4], alo[4][4], bhi[4][2], blo[4][2];
#pragma unroll
            for (int mt = 0; mt < 4; mt++) {
                int rb = (wm * 64 + mt * 16 + g) * SROW + kq + ks * 8;
                ahi[mt][0] = As_hi[rb];
                ahi[mt][1] = As_hi[rb + 8 * SROW];
                ahi[mt][2] = As_hi[rb + 4];
                ahi[mt][3] = As_hi[rb + 8 * SROW + 4];
                alo[mt][0] = As_lo[rb];
                alo[mt][1] = As_lo[rb + 8 * SROW];
                alo[mt][2] = As_lo[rb + 4];
                alo[mt][3] = As_lo[rb + 8 * SROW + 4];
            }
#pragma unroll
            for (int nt = 0; nt < 4; nt++) {
                int nb = (wn * 32 + nt * 8 + g) * SROW + kq + ks * 8;
                bhi[nt][0] = Bs_hi[nb];
                bhi[nt][1] = Bs_hi[nb + 4];
                blo[nt][0] = Bs_lo[nb];
                blo[nt][1] = Bs_lo[nb + 4];
            }
#pragma unroll
            for (int mt = 0; mt < 4; mt++)
#pragma unroll
                for (int nt = 0; nt < 4; nt++) {
                    float* d = acc[mt][nt];
                    mma16816(d[0], d[1], d[2], d[3],
                             ahi[mt][0], ahi[mt][1], ahi[mt][2], ahi[mt][3],
                             bhi[nt][0], bhi[nt][1]);
                    mma16816(d[0], d[1], d[2], d[3],
                             ahi[mt][0], ahi[mt][1], ahi[mt][2], ahi[mt][3],
                             blo[nt][0], blo[nt][1]);
                    mma16816(d[0], d[1], d[2], d[3],
                             alo[mt][0], alo[mt][1], alo[mt][2], alo[mt][3],
                             bhi[nt][0], bhi[nt][1]);
                }
        }
        __syncthreads();
    }

    // --- Epilogue: bias + store ---
#pragma unroll
    for (int mt = 0; mt < 4; mt++) {
#pragma unroll
        for (int nt = 0; nt < 4; nt++) {
            int row = m0 + wm * 64 + mt * 16 + g;
            int col = n0 + wn * 32 + nt * 8 + kq * 2;
            float b0 = bias[col], b1 = bias[col + 1];
            float2 v0 = make_float2(acc[mt][nt][0] + b0, acc[mt][nt][1] + b1);
            float2 v1 = make_float2(acc[mt][nt][2] + b0, acc[mt][nt][3] + b1);
            *(float2*)(g_xz + (size_t)row * G4 + col)       = v0;
            *(float2*)(g_xz + (size_t)(row + 8) * G4 + col) = v1;
        }
    }
}

// ---------------------------------------------------------------------------
// Phase 2: one timestep (unchanged from R2 passing version).
// ---------------------------------------------------------------------------
__device__ __forceinline__ float sigf(float v) {
    return 1.0f / (1.0f + expf(-v));
}

__global__ __launch_bounds__(256) void lstm_step_kernel(
    const float* __restrict__ R,    // [256, 1024]
    float* __restrict__ out,        // [256, 256]
    int t)
{
    __shared__ float As[16][16];
    __shared__ float Bs[16][128];
    __shared__ float Zs[16][128];

    const float* __restrict__ hprev = g_h[t & 1];
    float*       __restrict__ hnext = g_h[(t + 1) & 1];

    const int tid = threadIdx.x;
    const int hc0 = blockIdx.x * 32;
    const int b0  = blockIdx.y * 16;
    const int tx  = tid & 31;
    const int ty  = tid >> 5;

    float acc[2][4];
#pragma unroll
    for (int i = 0; i < 2; i++)
#pragma unroll
        for (int j = 0; j < 4; j++) acc[i][j] = 0.0f;

    for (int k0 = 0; k0 < Hh; k0 += 16) {
        {
            int m = tid >> 4;
            int k = tid & 15;
            As[k][m] = hprev[(b0 + m) * Hh + k0 + k];
        }
#pragma unroll
        for (int i = 0; i < 8; i++) {
            int e  = tid + i * 256;
            int kr = e >> 7;
            int cc = e & 127;
            int gcol = ((cc >> 5) << 8) + hc0 + (cc & 31);
            Bs[kr][cc] = R[(k0 + kr) * G4 + gcol];
        }
        __syncthreads();

#pragma unroll
        for (int kk = 0; kk < 16; kk++) {
            float a0 = As[kk][ty * 2];
            float a1 = As[kk][ty * 2 + 1];
            float4 b4 = *(const float4*)&Bs[kk][tx * 4];
            float br[4] = {b4.x, b4.y, b4.z, b4.w};
#pragma unroll
            for (int j = 0; j < 4; j++) {
                acc[0][j] = fmaf(a0, br[j], acc[0][j]);
                acc[1][j] = fmaf(a1, br[j], acc[1][j]);
            }
        }
        __syncthreads();
    }

#pragma unroll
    for (int rr = 0; rr < 2; rr++) {
        int r = ty * 2 + rr;
#pragma unroll
        for (int j = 0; j < 4; j++) {
            int cz   = tx * 4 + j;
            int gcol = ((cz >> 5) << 8) + hc0 + (cz & 31);
            size_t xzoff = ((size_t)(b0 + r) * Tt + t) * G4 + gcol;
            Zs[r][cz] = acc[rr][j] + g_xz[xzoff];
        }
    }
    __syncthreads();

#pragma unroll
    for (int i = 0; i < 2; i++) {
        int e  = tid + i * 256;
        int r  = e >> 5;
        int hh = e & 31;
        float zi = Zs[r][hh];
        float zf = Zs[r][32 + hh];
        float zg = Zs[r][64 + hh];
        float zo = Zs[r][96 + hh];

        int idx = (b0 + r) * Hh + hc0 + hh;
        float cn = sigf(zf) * g_c[idx] + sigf(zi) * tanhf(zg);
        g_c[idx] = cn;
        float hn = sigf(zo) * tanhf(cn);
        hnext[idx] = hn;
        if (t == Tt - 1) out[idx] = hn;
    }
}

// ---------------------------------------------------------------------------
// Launch
// ---------------------------------------------------------------------------
extern "C" void kernel_launch(void* const* d_in, const int* in_sizes, int n_in,
                              void* d_out, int out_size)
{
    const float* x    = (const float*)d_in[0];   // [256, 128, 1280]
    const float* W    = (const float*)d_in[1];   // [1280, 1024]
    const float* R    = (const float*)d_in[2];   // [256, 1024]
    const float* bias = (const float*)d_in[3];   // [1024]
    float* out = (float*)d_out;                  // [256, 256]

    (void)in_sizes; (void)n_in; (void)out_size;

    init_state_kernel<<<(Bm * Hh + 511) / 512, 512>>>();

    // W transpose + bf16 hi/lo split
    convert_w_kernel<<<dim3(G4 / 32, Ff / 32), dim3(32, 8)>>>(W);

    // Phase 1: xz = x @ W + bias (split-bf16 tensor cores)
    gemm_xz_kernel<<<dim3(G4 / 128, (Bm * Tt) / 128), 256>>>(x, bias);

    // Phase 2: 128 sequential timesteps
    for (int t = 0; t < Tt; t++) {
        lstm_step_kernel<<<dim3(Hh / 32, Bm / 16), 256>>>(R, out, t);
    }
}

// round 6
// speedup vs baseline: 1.4633x; 1.1529x over previous
#include <cuda_runtime.h>
#include <cuda_bf16.h>
#include <math.h>
#include <stdint.h>

// Problem constants
#define Bm 256      // batch
#define Tt 128      // timesteps
#define Ff 1280     // features
#define Hh 256      // hidden
#define G4 1024     // 4*H

// ---------------------------------------------------------------------------
// Scratch (allocation-free: __device__ globals)
// ---------------------------------------------------------------------------
__device__ float g_xz[(size_t)Bm * Tt * G4];          // x@W + bias, [B*T, 4H]
__device__ float g_h[2][Bm * Hh];                      // ping-pong hidden state
__device__ float g_c[Bm * Hh];                         // cell state
__device__ __nv_bfloat16 g_Wt_hi[(size_t)G4 * Ff];     // W^T hi split, [1024][1280]
__device__ __nv_bfloat16 g_Wt_lo[(size_t)G4 * Ff];     // W^T lo split
__device__ __nv_bfloat16 g_x_hi[(size_t)Bm * Tt * Ff]; // x hi split
__device__ __nv_bfloat16 g_x_lo[(size_t)Bm * Tt * Ff]; // x lo split

// ---------------------------------------------------------------------------
// Init: zero h0, c0
// ---------------------------------------------------------------------------
__global__ void init_state_kernel() {
    int idx = blockIdx.x * blockDim.x + threadIdx.x;
    if (idx < Bm * Hh) {
        g_h[0][idx] = 0.0f;
        g_c[idx]    = 0.0f;
    }
}

__device__ __forceinline__ uint32_t pack_bf16(__nv_bfloat16 a, __nv_bfloat16 b) {
    uint32_t lo16 = (uint32_t)__bfloat16_as_ushort(a);
    uint32_t hi16 = (uint32_t)__bfloat16_as_ushort(b);
    return lo16 | (hi16 << 16);
}

// ---------------------------------------------------------------------------
// x -> bf16 hi/lo split (one shot, memory bound)
// ---------------------------------------------------------------------------
__global__ __launch_bounds__(256) void convert_x_kernel(const float* __restrict__ x) {
    size_t i = (size_t)blockIdx.x * blockDim.x + threadIdx.x;   // float4 index
    const size_t n4 = (size_t)Bm * Tt * Ff / 4;
    if (i >= n4) return;
    float4 v = ((const float4*)x)[i];
    __nv_bfloat16 hx = __float2bfloat16_rn(v.x);
    __nv_bfloat16 hy = __float2bfloat16_rn(v.y);
    __nv_bfloat16 hz = __float2bfloat16_rn(v.z);
    __nv_bfloat16 hw = __float2bfloat16_rn(v.w);
    __nv_bfloat16 lx = __float2bfloat16_rn(v.x - __bfloat162float(hx));
    __nv_bfloat16 ly = __float2bfloat16_rn(v.y - __bfloat162float(hy));
    __nv_bfloat16 lz = __float2bfloat16_rn(v.z - __bfloat162float(hz));
    __nv_bfloat16 lw = __float2bfloat16_rn(v.w - __bfloat162float(hw));
    ((uint2*)g_x_hi)[i] = make_uint2(pack_bf16(hx, hy), pack_bf16(hz, hw));
    ((uint2*)g_x_lo)[i] = make_uint2(pack_bf16(lx, ly), pack_bf16(lz, lw));
}

// ---------------------------------------------------------------------------
// W transpose + bf16 hi/lo split: Wt[n][k] = split(W[k][n])
// ---------------------------------------------------------------------------
__global__ __launch_bounds__(256) void convert_w_kernel(const float* __restrict__ W) {
    __shared__ float tile[32][33];
    const int nb = blockIdx.x * 32;
    const int kb = blockIdx.y * 32;
    const int tx = threadIdx.x;
    const int ty = threadIdx.y;

#pragma unroll
    for (int j = 0; j < 32; j += 8)
        tile[ty + j][tx] = W[(size_t)(kb + ty + j) * G4 + nb + tx];
    __syncthreads();

#pragma unroll
    for (int j = 0; j < 32; j += 8) {
        float v = tile[tx][ty + j];
        __nv_bfloat16 hi = __float2bfloat16_rn(v);
        __nv_bfloat16 lo = __float2bfloat16_rn(v - __bfloat162float(hi));
        size_t off = (size_t)(nb + ty + j) * Ff + kb + tx;
        g_Wt_hi[off] = hi;
        g_Wt_lo[off] = lo;
    }
}

// ---------------------------------------------------------------------------
// Phase 1 GEMM: xz = x @ W + bias via split-bf16 mma.sync (3 products).
// 128x128 block tile, BK=16 halves, 3-stage cp.async pipeline, ldmatrix frags.
// Smem: 32B rows, XOR swizzle (chunk ^= (row>>2)&1) -> conflict-free, no pad.
// Static smem: 3 stages x 4 matrices x 4KB = 48KB exactly.
// ---------------------------------------------------------------------------
#define MAT_B 4096                      // bytes per matrix tile (128 x 32B)
#define A_HI_OFF 0
#define A_LO_OFF (1 * MAT_B)
#define B_HI_OFF (2 * MAT_B)
#define B_LO_OFF (3 * MAT_B)
#define STAGE_B (4 * MAT_B)             // 16384
#define NSTAGE 3
#define NKT (Ff / 16)                   // 80 k-tiles

__device__ __forceinline__ void cpasync16(uint32_t saddr, const void* gaddr) {
    asm volatile("cp.async.cg.shared.global [%0], [%1], 16;\n"
                 :: "r"(saddr), "l"(gaddr));
}
__device__ __forceinline__ void cp_commit() {
    asm volatile("cp.async.commit_group;\n");
}
template <int N>
__device__ __forceinline__ void cp_wait() {
    asm volatile("cp.async.wait_group %0;\n" :: "n"(N));
}
__device__ __forceinline__ void ldsm_x4(uint32_t& r0, uint32_t& r1,
                                        uint32_t& r2, uint32_t& r3, uint32_t a) {
    asm volatile("ldmatrix.sync.aligned.m8n8.x4.shared.b16 {%0,%1,%2,%3}, [%4];\n"
                 : "=r"(r0), "=r"(r1), "=r"(r2), "=r"(r3) : "r"(a));
}
__device__ __forceinline__ void mma16816(
    float& d0, float& d1, float& d2, float& d3,
    uint32_t a0, uint32_t a1, uint32_t a2, uint32_t a3,
    uint32_t b0, uint32_t b1)
{
    asm volatile(
        "mma.sync.aligned.m16n8k16.row.col.f32.bf16.bf16.f32 "
        "{%0,%1,%2,%3}, {%4,%5,%6,%7}, {%8,%9}, {%0,%1,%2,%3};\n"
        : "+f"(d0), "+f"(d1), "+f"(d2), "+f"(d3)
        : "r"(a0), "r"(a1), "r"(a2), "r"(a3), "r"(b0), "r"(b1));
}

// swizzled byte offset within one matrix tile: row (0..127), chunk (0..1)
__device__ __forceinline__ uint32_t sw_off(int row, int chunk) {
    return (uint32_t)(row * 32 + ((chunk ^ ((row >> 2) & 1)) << 4));
}

__global__ __launch_bounds__(256) void gemm_xz_kernel(const float* __restrict__ bias)
{
    __shared__ __align__(16) unsigned char smem[NSTAGE * STAGE_B];   // 48KB

    const int tid  = threadIdx.x;
    const int lane = tid & 31;
    const int wid  = tid >> 5;
    const int wm   = wid >> 2;         // 0..1 -> m offset wm*64
    const int wn   = wid & 3;          // 0..3 -> n offset wn*32
    const int m0   = blockIdx.y * 128;
    const int n0   = blockIdx.x * 128;
    const int g    = lane >> 2;        // fragment row group
    const int kq   = lane & 3;         // fragment k pair

    const uint32_t smem_u32 = (uint32_t)__cvta_generic_to_shared(smem);

    // cp.async coords: one 16B chunk per matrix per thread
    const int l_row = tid >> 1;        // 0..127
    const int l_ch  = tid & 1;         // chunk 0/1
    const uint32_t l_soff = sw_off(l_row, l_ch);

    float acc[4][4][4];
#pragma unroll
    for (int i = 0; i < 4; i++)
#pragma unroll
        for (int j = 0; j < 4; j++)
#pragma unroll
            for (int r = 0; r < 4; r++) acc[i][j][r] = 0.0f;

    auto load_stage = [&](int kt, int s) {
        const int k0 = kt * 16;
        const uint32_t sb = smem_u32 + s * STAGE_B;
        size_t ga = (size_t)(m0 + l_row) * Ff + k0 + l_ch * 8;
        size_t gb = (size_t)(n0 + l_row) * Ff + k0 + l_ch * 8;
        cpasync16(sb + A_HI_OFF + l_soff, g_x_hi + ga);
        cpasync16(sb + A_LO_OFF + l_soff, g_x_lo + ga);
        cpasync16(sb + B_HI_OFF + l_soff, g_Wt_hi + gb);
        cpasync16(sb + B_LO_OFF + l_soff, g_Wt_lo + gb);
    };

    // fragment lane coords
    const int a_row = lane & 15;            // row within 16-row tile
    const int a_kc  = lane >> 4;            // k chunk 0/1
    const int b_row = lane & 7;             // n within 8-col tile
    const int b_kc  = (lane >> 3) & 1;      // k chunk 0/1
    const int b_tl  = (lane >> 4) & 1;      // which of 2 n-tiles in this ldsm

    // ---- prologue: stages 0,1 ----
    load_stage(0, 0); cp_commit();
    load_stage(1, 1); cp_commit();

    int s_cur = 0, s_nxt = 2;
    for (int kt = 0; kt < NKT; kt++) {
        if (kt == NKT - 1) cp_wait<0>(); else cp_wait<1>();
        __syncthreads();

        if (kt + 2 < NKT) {
            load_stage(kt + 2, s_nxt);
            cp_commit();
        }

        const uint32_t sb = smem_u32 + s_cur * STAGE_B;

        uint32_t ahi[4][4], alo[4][4], bhi[4][2], blo[4][2];
#pragma unroll
        for (int mt = 0; mt < 4; mt++) {
            int row = wm * 64 + mt * 16 + a_row;
            uint32_t off = sw_off(row, a_kc);
            ldsm_x4(ahi[mt][0], ahi[mt][1], ahi[mt][2], ahi[mt][3],
                    sb + A_HI_OFF + off);
            ldsm_x4(alo[mt][0], alo[mt][1], alo[mt][2], alo[mt][3],
                    sb + A_LO_OFF + off);
        }
#pragma unroll
        for (int bt = 0; bt < 2; bt++) {
            int row = wn * 32 + (2 * bt + b_tl) * 8 + b_row;
            uint32_t off = sw_off(row, b_kc);
            ldsm_x4(bhi[2 * bt][0], bhi[2 * bt][1],
                    bhi[2 * bt + 1][0], bhi[2 * bt + 1][1],
                    sb + B_HI_OFF + off);
            ldsm_x4(blo[2 * bt][0], blo[2 * bt][1],
                    blo[2 * bt + 1][0], blo[2 * bt + 1][1],
                    sb + B_LO_OFF + off);
        }
#pragma unroll
        for (int mt = 0; mt < 4; mt++)
#pragma unroll
            for (int nt = 0; nt < 4; nt++) {
                float* d = acc[mt][nt];
                mma16816(d[0], d[1], d[2], d[3],
                         ahi[mt][0], ahi[mt][1], ahi[mt][2], ahi[mt][3],
                         bhi[nt][0], bhi[nt][1]);
                mma16816(d[0], d[1], d[2], d[3],
                         ahi[mt][0], ahi[mt][1], ahi[mt][2], ahi[mt][3],
                         blo[nt][0], blo[nt][1]);
                mma16816(d[0], d[1], d[2], d[3],
                         alo[mt][0], alo[mt][1], alo[mt][2], alo[mt][3],
                         bhi[nt][0], bhi[nt][1]);
            }

        s_cur = (s_cur == 2) ? 0 : s_cur + 1;
        s_nxt = (s_nxt == 2) ? 0 : s_nxt + 1;
    }

    // ---- epilogue: bias + store ----
#pragma unroll
    for (int mt = 0; mt < 4; mt++) {
#pragma unroll
        for (int nt = 0; nt < 4; nt++) {
            int row = m0 + wm * 64 + mt * 16 + g;
            int col = n0 + wn * 32 + nt * 8 + kq * 2;
            float b0 = bias[col], b1 = bias[col + 1];
            float2 v0 = make_float2(acc[mt][nt][0] + b0, acc[mt][nt][1] + b1);
            float2 v1 = make_float2(acc[mt][nt][2] + b0, acc[mt][nt][3] + b1);
            *(float2*)(g_xz + (size_t)row * G4 + col)       = v0;
            *(float2*)(g_xz + (size_t)(row + 8) * G4 + col) = v1;
        }
    }
}

// ---------------------------------------------------------------------------
// Phase 2: one timestep (unchanged — passing since R2).
// ---------------------------------------------------------------------------
__device__ __forceinline__ float sigf(float v) {
    return 1.0f / (1.0f + expf(-v));
}

__global__ __launch_bounds__(256) void lstm_step_kernel(
    const float* __restrict__ R,    // [256, 1024]
    float* __restrict__ out,        // [256, 256]
    int t)
{
    __shared__ float As[16][16];
    __shared__ float Bs[16][128];
    __shared__ float Zs[16][128];

    const float* __restrict__ hprev = g_h[t & 1];
    float*       __restrict__ hnext = g_h[(t + 1) & 1];

    const int tid = threadIdx.x;
    const int hc0 = blockIdx.x * 32;
    const int b0  = blockIdx.y * 16;
    const int tx  = tid & 31;
    const int ty  = tid >> 5;

    float acc[2][4];
#pragma unroll
    for (int i = 0; i < 2; i++)
#pragma unroll
        for (int j = 0; j < 4; j++) acc[i][j] = 0.0f;

    for (int k0 = 0; k0 < Hh; k0 += 16) {
        {
            int m = tid >> 4;
            int k = tid & 15;
            As[k][m] = hprev[(b0 + m) * Hh + k0 + k];
        }
#pragma unroll
        for (int i = 0; i < 8; i++) {
            int e  = tid + i * 256;
            int kr = e >> 7;
            int cc = e & 127;
            int gcol = ((cc >> 5) << 8) + hc0 + (cc & 31);
            Bs[kr][cc] = R[(k0 + kr) * G4 + gcol];
        }
        __syncthreads();

#pragma unroll
        for (int kk = 0; kk < 16; kk++) {
            float a0 = As[kk][ty * 2];
            float a1 = As[kk][ty * 2 + 1];
            float4 b4 = *(const float4*)&Bs[kk][tx * 4];
            float br[4] = {b4.x, b4.y, b4.z, b4.w};
#pragma unroll
            for (int j = 0; j < 4; j++) {
                acc[0][j] = fmaf(a0, br[j], acc[0][j]);
                acc[1][j] = fmaf(a1, br[j], acc[1][j]);
            }
        }
        __syncthreads();
    }

#pragma unroll
    for (int rr = 0; rr < 2; rr++) {
        int r = ty * 2 + rr;
#pragma unroll
        for (int j = 0; j < 4; j++) {
            int cz   = tx * 4 + j;
            int gcol = ((cz >> 5) << 8) + hc0 + (cz & 31);
            size_t xzoff = ((size_t)(b0 + r) * Tt + t) * G4 + gcol;
            Zs[r][cz] = acc[rr][j] + g_xz[xzoff];
        }
    }
    __syncthreads();

#pragma unroll
    for (int i = 0; i < 2; i++) {
        int e  = tid + i * 256;
        int r  = e >> 5;
        int hh = e & 31;
        float zi = Zs[r][hh];
        float zf = Zs[r][32 + hh];
        float zg = Zs[r][64 + hh];
        float zo = Zs[r][96 + hh];

        int idx = (b0 + r) * Hh + hc0 + hh;
        float cn = sigf(zf) * g_c[idx] + sigf(zi) * tanhf(zg);
        g_c[idx] = cn;
        float hn = sigf(zo) * tanhf(cn);
        hnext[idx] = hn;
        if (t == Tt - 1) out[idx] = hn;
    }
}

// ---------------------------------------------------------------------------
// Launch (stateless, branch-free, capture-safe)
// ---------------------------------------------------------------------------
extern "C" void kernel_launch(void* const* d_in, const int* in_sizes, int n_in,
                              void* d_out, int out_size)
{
    const float* x    = (const float*)d_in[0];   // [256, 128, 1280]
    const float* W    = (const float*)d_in[1];   // [1280, 1024]
    const float* R    = (const float*)d_in[2];   // [256, 1024]
    const float* bias = (const float*)d_in[3];   // [1024]
    float* out = (float*)d_out;                  // [256, 256]

    (void)in_sizes; (void)n_in; (void)out_size;

    init_state_kernel<<<(Bm * Hh + 511) / 512, 512>>>();

    // One-shot conversions
    convert_w_kernel<<<dim3(G4 / 32, Ff / 32), dim3(32, 8)>>>(W);
    convert_x_kernel<<<(unsigned)(((size_t)Bm * Tt * Ff / 4 + 255) / 256), 256>>>(x);

    // Phase 1: xz = x @ W + bias (tensor cores, 3-stage cp.async, static smem)
    gemm_xz_kernel<<<dim3(G4 / 128, (Bm * Tt) / 128), 256>>>(bias);

    // Phase 2: 128 sequential timesteps
    for (int t = 0; t < Tt; t++) {
        lstm_step_kernel<<<dim3(Hh / 32, Bm / 16), 256>>>(R, out, t);
    }
}